// round 14
// baseline (speedup 1.0000x reference)
#include <cuda_runtime.h>
#include <cuda_fp16.h>
#include <cstdint>
#include <math.h>

#define B_    8
#define S_    2048
#define HID_  1024
#define NH_   16
#define HD_   64
#define SP_   1024
#define NQKV_ 3072
#define QSCALE 0.18033688f   // 0.125 * log2(e)

// ---------------- scratch ----------------------------------------------------
__device__ __half g_ah[B_*S_*HID_];       // half hidden
__device__ __half g_wh[NQKV_*HID_];       // half Wqkv
__device__ __half g_qs[B_*S_*HID_];       // q pre-pool (half)
__device__ __half g_kh[B_*NH_*S_*HD_];    // roped K half
__device__ __half g_vh[B_*NH_*S_*HD_];    // V half
__device__ float2 g_rope[S_*32];          // (cos, sin) per (pos, freq)
__device__ int    g_len[B_];

// ---------------- helpers -----------------------------------------------------
__device__ __forceinline__ void mma_f16(float* d,
        unsigned a0, unsigned a1, unsigned a2, unsigned a3,
        unsigned b0, unsigned b1) {
    asm volatile("mma.sync.aligned.m16n8k16.row.col.f32.f16.f16.f32 "
        "{%0,%1,%2,%3},{%4,%5,%6,%7},{%8,%9},{%0,%1,%2,%3};\n"
        : "+f"(d[0]), "+f"(d[1]), "+f"(d[2]), "+f"(d[3])
        : "r"(a0), "r"(a1), "r"(a2), "r"(a3), "r"(b0), "r"(b1));
}
__device__ __forceinline__ unsigned pk(float lo, float hi) {
    __half2 h = __floats2half2_rn(lo, hi);
    return *reinterpret_cast<unsigned*>(&h);
}
__device__ __forceinline__ float2 up(unsigned x) {
    return __half22float2(*reinterpret_cast<__half2*>(&x));
}
__device__ __forceinline__ unsigned ex2h2(unsigned x) {
    unsigned r; asm("ex2.approx.f16x2 %0, %1;" : "=r"(r) : "r"(x)); return r;
}
__device__ __forceinline__ uint32_t smem_u32(const void* p) {
    uint32_t a;
    asm("{ .reg .u64 t; cvta.to.shared.u64 t, %1; cvt.u32.u64 %0, t; }"
        : "=r"(a) : "l"(p));
    return a;
}
__device__ __forceinline__ void cp16(uint32_t saddr, const void* gptr) {
    asm volatile("cp.async.cg.shared.global [%0], [%1], 16;"
                 :: "r"(saddr), "l"(gptr));
}
__device__ __forceinline__ void cp_commit() { asm volatile("cp.async.commit_group;"); }
template <int N>
__device__ __forceinline__ void cp_wait() {
    asm volatile("cp.async.wait_group %0;" :: "n"(N));
}
__device__ __forceinline__ void ldsm4(unsigned& r0, unsigned& r1, unsigned& r2,
                                      unsigned& r3, uint32_t addr) {
    asm volatile("ldmatrix.sync.aligned.m8n8.x4.shared.b16 {%0,%1,%2,%3}, [%4];"
        : "=r"(r0), "=r"(r1), "=r"(r2), "=r"(r3) : "r"(addr));
}
__device__ __forceinline__ void ldsm4t(unsigned& r0, unsigned& r1, unsigned& r2,
                                       unsigned& r3, uint32_t addr) {
    asm volatile("ldmatrix.sync.aligned.m8n8.x4.trans.shared.b16 {%0,%1,%2,%3}, [%4];"
        : "=r"(r0), "=r"(r1), "=r"(r2), "=r"(r3) : "r"(addr));
}

// ---------------- kernel 1: half pre-convert + rope table + lengths -----------
// MLP=2: each thread handles two independent elements.
#define A4_ (B_*S_*HID_/4)
#define W4_ (NQKV_*HID_/4)
#define RT_ (S_*32)
#define CVT_TOT (A4_ + W4_ + RT_)
__device__ __forceinline__ void cvt_one(int i, const float* hidden, const float* W) {
    if (i < A4_) {
        float4 v = ((const float4*)hidden)[i];
        ((uint2*)g_ah)[i] = make_uint2(pk(v.x, v.y), pk(v.z, v.w));
    } else if (i < A4_ + W4_) {
        int j = i - A4_;
        float4 v = ((const float4*)W)[j];
        ((uint2*)g_wh)[j] = make_uint2(pk(v.x, v.y), pk(v.z, v.w));
    } else {
        int e = i - A4_ - W4_;
        if (e < RT_) {
            int s = e >> 5, ir = e & 31;
            float theta = __expf(-(float)ir * (9.210340371976184f / 32.0f));
            float sn, cs;
            sincosf((float)s * theta, &sn, &cs);
            g_rope[e] = make_float2(cs, sn);
        }
    }
}
__global__ void cvtlen_kernel(const float* __restrict__ hidden,
                              const float* __restrict__ W,
                              const void*  __restrict__ mask) {
    int i0 = blockIdx.x * 512 + threadIdx.x;
    cvt_one(i0, hidden, W);
    cvt_one(i0 + 256, hidden, W);
    if (blockIdx.x == 0) {
        __shared__ int sred[256];
        const int* mi = (const int*)mask;
        int w = mi[16];
        int mode = (w == 1) ? 0 : ((w == 0x3F800000) ? 1 : 2);
        for (int b = 0; b < B_; b++) {
            int cnt = 0;
            for (int s = threadIdx.x; s < S_; s += 256) {
                int v;
                if (mode == 0)      v = (mi[b*S_+s] != 0);
                else if (mode == 1) v = (((const float*)mask)[b*S_+s] != 0.0f);
                else                v = (((const unsigned char*)mask)[b*S_+s] != 0);
                cnt += v;
            }
            sred[threadIdx.x] = cnt;
            __syncthreads();
            for (int st = 128; st > 0; st >>= 1) {
                if (threadIdx.x < st) sred[threadIdx.x] += sred[threadIdx.x + st];
                __syncthreads();
            }
            if (threadIdx.x == 0) g_len[b] = sred[0];
            __syncthreads();
        }
    }
}

// ---------------- kernel 2: QKV GEMM fp16, 128x128 tile, BK=64, 3-stage -------
// 256 threads = 8 warps (2x4), warp 64x32, 2 CTAs/SM.
// bm remap: s-block-major across batches -> dead early-exit blocks schedule LAST.
#define AST_H (128*72)              // halfs per stage (pitch 72)
#define BSTART (3*AST_H)
#define GEMM_SMEM (6*AST_H*2)       // 110592 B
__global__ __launch_bounds__(256, 2) void qkv_gemm_h(const float* __restrict__ bias) {
    const int by = blockIdx.y, bn = blockIdx.x;
    const int bm = (by & 7) * 16 + (by >> 3);   // b*16 + sblk
    {
        int bb0 = bm >> 4;
        int s00 = (bm & 15) * 128;
        if (s00 >= g_len[bb0]) return;     // dead rows: outputs never read
    }
    extern __shared__ __half hs[];
    const uint32_t sb = smem_u32(hs);
    const int tid = threadIdx.x, warp = tid >> 5, lane = tid & 31;
    const int wm = warp >> 2, wn = warp & 3;
    const int g = lane >> 2, c = lane & 3;
    const __half* Ab = g_ah + (size_t)bm * 128 * HID_;
    const __half* Wb = g_wh + (size_t)bn * 128 * HID_;

#define GISSUE(st, kt) do {                                                        \
        _Pragma("unroll")                                                          \
        for (int ii = 0; ii < 8; ii++) {                                           \
            int e = tid + ii*256;                                                  \
            if (e < 1024) {                                                        \
                int row = e >> 3, ch = e & 7;                                      \
                cp16(sb + ((st)*AST_H + row*72 + ch*8)*2,                          \
                     Ab + (size_t)row*HID_ + (kt)*64 + ch*8);                      \
            } else {                                                               \
                int e2 = e - 1024;                                                 \
                int row = e2 >> 3, ch = e2 & 7;                                    \
                cp16(sb + (BSTART + (st)*AST_H + row*72 + ch*8)*2,                 \
                     Wb + (size_t)row*HID_ + (kt)*64 + ch*8);                      \
            }                                                                      \
        }                                                                          \
    } while (0)

    float acc[4][4][4];
#pragma unroll
    for (int i = 0; i < 4; i++)
#pragma unroll
        for (int j = 0; j < 4; j++)
#pragma unroll
            for (int r = 0; r < 4; r++) acc[i][j][r] = 0.0f;

    GISSUE(0, 0); cp_commit();
    GISSUE(1, 1); cp_commit();

    const int l8  = ((lane >> 3) & 1) * 8;
    const int l16 = ((lane >> 4) & 1) * 8;
    for (int kt = 0; kt < 16; kt++) {
        if (kt + 1 < 16) cp_wait<1>(); else cp_wait<0>();
        __syncthreads();
        if (kt + 2 < 16) { GISSUE((kt + 2) % 3, kt + 2); cp_commit(); }

        const uint32_t abase = sb + ((kt % 3) * AST_H) * 2;
        const uint32_t bbase = sb + (BSTART + (kt % 3) * AST_H) * 2;
#pragma unroll
        for (int ks = 0; ks < 4; ks++) {
            unsigned a[4][4], bf[4][2];
#pragma unroll
            for (int i = 0; i < 4; i++) {
                uint32_t ad = abase +
                    ((wm*64 + i*16 + (lane&7) + l8)*72 + ks*16 + l16)*2;
                ldsm4(a[i][0], a[i][1], a[i][2], a[i][3], ad);
            }
#pragma unroll
            for (int jp = 0; jp < 2; jp++) {
                uint32_t bd = bbase +
                    ((wn*32 + jp*16 + (lane&7) + l16)*72 + ks*16 + l8)*2;
                ldsm4(bf[2*jp][0], bf[2*jp][1], bf[2*jp+1][0], bf[2*jp+1][1], bd);
            }
#pragma unroll
            for (int i = 0; i < 4; i++)
#pragma unroll
                for (int j = 0; j < 4; j++)
                    mma_f16(acc[i][j], a[i][0], a[i][1], a[i][2], a[i][3],
                            bf[j][0], bf[j][1]);
        }
    }

    // epilogue: bias; q -> half staging; K -> RoPE (table) -> half; V -> half
#pragma unroll
    for (int i = 0; i < 4; i++) {
#pragma unroll
        for (int hh = 0; hh < 2; hh++) {
            int m = bm*128 + wm*64 + i*16 + hh*8 + g;
            int bb2 = m >> 11;
            int sq = m & 2047;
#pragma unroll
            for (int j = 0; j < 4; j++) {
                int n = bn*128 + wn*32 + j*8 + 2*c;
                float v0 = acc[i][j][hh*2+0] + bias[n];
                float v1 = acc[i][j][hh*2+1] + bias[n+1];
                if (n < 1024) {
                    *(unsigned*)&g_qs[((size_t)(bb2*S_+sq))*HID_ + n] = pk(v0, v1);
                } else if (n < 2048) {
                    int nn = n - 1024, hd = nn >> 6, dd = nn & 63;
                    float2 cs = g_rope[sq*32 + (dd >> 1)];
                    *(unsigned*)&g_kh[(((size_t)(bb2*NH_+hd))*S_ + sq)*HD_ + dd] =
                        pk(v0*cs.x - v1*cs.y, v1*cs.x + v0*cs.y);
                } else {
                    int nn = n - 2048, hd = nn >> 6, dd = nn & 63;
                    *(unsigned*)&g_vh[(((size_t)(bb2*NH_+hd))*S_ + sq)*HD_ + dd] = pk(v0, v1);
                }
            }
        }
    }
}

// ---------------- kernel 3: flash attention fp16, fused pool+RoPE-Q -----------
// grid (NH, B, SP/128): qt on z so dead q-tiles (high qt) schedule LAST.
// smem halfs: Q[128][72] @0; K(buf) @9216+buf*18432; V(buf) @18432+buf*18432.
#define ATTN_SMEM (46080*2)   // 92160 B
__global__ __launch_bounds__(256, 2) void attn_h(float* __restrict__ out) {
    extern __shared__ __half hs[];
    const uint32_t sb = smem_u32(hs);
    const int h = blockIdx.x, b = blockIdx.y, qt = blockIdx.z;
    const int len = g_len[b];
    const int tid = threadIdx.x, warp = tid >> 5, lane = tid & 31;
    const int g = lane >> 2, c = lane & 3;

    // ---- dead q-tile: all rows masked -> write zeros, skip everything ----
    const int plen = (len + 1) >> 1;
    if (qt * 128 >= plen) {
#pragma unroll
        for (int ii = 0; ii < 8; ii++) {
            int e = tid + ii*256;             // 2048 float4 = 128 rows x 16 f4
            int r = e >> 4, c4 = e & 15;
            *(float4*)&out[((size_t)(b*SP_ + qt*128 + r))*(NH_*HD_) + h*HD_ + c4*4] =
                make_float4(0.f, 0.f, 0.f, 0.f);
        }
        return;
    }

    const int l8  = ((lane >> 3) & 1) * 8;
    const int l16 = ((lane >> 4) & 1) * 8;
    const size_t khb = (size_t)(b*NH_+h)*S_*HD_;

#define KVLOAD(buf, kt) do {                                                       \
        _Pragma("unroll")                                                          \
        for (int ii = 0; ii < 8; ii++) {                                           \
            int e = tid + ii*256;                                                  \
            if (e < 1024) {                                                        \
                int row = e >> 3, ch = e & 7;                                      \
                cp16(sb + (9216 + (buf)*18432 + row*72 + ch*8)*2,                  \
                     g_kh + khb + (size_t)((kt)*128+row)*HD_ + ch*8);              \
            } else {                                                               \
                int e2 = e - 1024;                                                 \
                int row = e2 >> 3, ch = e2 & 7;                                    \
                cp16(sb + (18432 + (buf)*18432 + row*72 + ch*8)*2,                 \
                     g_vh + khb + (size_t)((kt)*128+row)*HD_ + ch*8);              \
            }                                                                      \
        }                                                                          \
    } while (0)
    KVLOAD(0, 0);
    cp_commit();

    // fused pool + RoPE + scale for Q tile (overlaps the KV loads above)
#pragma unroll
    for (int ii = 0; ii < 16; ii++) {
        int e = tid + ii*256;                  // 4096 = 128 rows x 32 pairs
        int r = e >> 5, i = e & 31;
        int p = qt*128 + r;
        int s0 = 2 * p;
        int c0 = (s0 < len), c1 = (s0 + 1 < len);
        float norm = (c0 + c1 > 0) ? (float)(c0 + c1) : 1.0f;
        const __half* row0 = g_qs + ((size_t)(b*S_+s0))*HID_ + h*HD_ + 2*i;
        float2 a = c0 ? __half22float2(*(const __half2*)row0) : make_float2(0.f, 0.f);
        float2 d = c1 ? __half22float2(*(const __half2*)(row0 + HID_)) : make_float2(0.f, 0.f);
        float x0 = (a.x + d.x) / norm;
        float x1 = (a.y + d.y) / norm;
        float2 cs = g_rope[p*32 + i];
        *(unsigned*)&hs[r*72 + 2*i] =
            pk((x0*cs.x - x1*cs.y)*QSCALE, (x1*cs.x + x0*cs.y)*QSCALE);
    }

    float O[8][4];
    float m0 = -1e30f, m1 = -1e30f, lq0 = 0.0f, lq1 = 0.0f;
#pragma unroll
    for (int nt = 0; nt < 8; nt++)
#pragma unroll
        for (int r = 0; r < 4; r++) O[nt][r] = 0.0f;

    const int ntiles = (len + 127) >> 7;
    int buf = 0;

    for (int kt = 0; kt < ntiles; kt++) {
        if (kt + 1 < ntiles) { KVLOAD(buf ^ 1, kt + 1); cp_commit(); cp_wait<1>(); }
        else cp_wait<0>();
        __syncthreads();

        // ---- S = Q K^T  (all frags via ldmatrix.x4) ----
        float s[16][4];
#pragma unroll
        for (int nt = 0; nt < 16; nt++)
#pragma unroll
            for (int r = 0; r < 4; r++) s[nt][r] = 0.0f;

        const int kH = 9216 + buf*18432;
#pragma unroll
        for (int ks = 0; ks < 4; ks++) {
            uint32_t ad = sb + ((warp*16 + (lane&7) + l8)*72 + ks*16 + l16)*2;
            unsigned a0, a1, a2, a3;
            ldsm4(a0, a1, a2, a3, ad);
#pragma unroll
            for (int ntp = 0; ntp < 8; ntp++) {
                uint32_t bd = sb + (kH + (ntp*16 + (lane&7) + l16)*72 + ks*16 + l8)*2;
                unsigned b0, b1, b2, b3;
                ldsm4(b0, b1, b2, b3, bd);
                mma_f16(s[2*ntp],   a0, a1, a2, a3, b0, b1);
                mma_f16(s[2*ntp+1], a0, a1, a2, a3, b2, b3);
            }
        }

        // ---- mask partial tile ----
        if (kt == ntiles - 1 && (len & 127)) {
#pragma unroll
            for (int nt = 0; nt < 16; nt++)
#pragma unroll
                for (int cc = 0; cc < 2; cc++) {
                    int kcol = kt*128 + nt*8 + 2*c + cc;
                    if (kcol >= len) { s[nt][cc] = -1e30f; s[nt][2+cc] = -1e30f; }
                }
        }

        // ---- online max + corr ----
        float mx0 = -1e30f, mx1 = -1e30f;
#pragma unroll
        for (int nt = 0; nt < 16; nt++) {
            mx0 = fmaxf(mx0, fmaxf(s[nt][0], s[nt][1]));
            mx1 = fmaxf(mx1, fmaxf(s[nt][2], s[nt][3]));
        }
        mx0 = fmaxf(mx0, __shfl_xor_sync(0xffffffffu, mx0, 1));
        mx0 = fmaxf(mx0, __shfl_xor_sync(0xffffffffu, mx0, 2));
        mx1 = fmaxf(mx1, __shfl_xor_sync(0xffffffffu, mx1, 1));
        mx1 = fmaxf(mx1, __shfl_xor_sync(0xffffffffu, mx1, 2));
        float mn0 = fmaxf(m0, mx0), mn1 = fmaxf(m1, mx1);
        float cr0 = exp2f(m0 - mn0), cr1 = exp2f(m1 - mn1);
        m0 = mn0; m1 = mn1;

        // ---- exp in fp16x2 (packed = PV a-frags); f32 row sums on FMA pipe ----
        unsigned ph[16][2];
        float r0 = 0.0f, r1 = 0.0f;
#pragma unroll
        for (int nt = 0; nt < 16; nt++) {
            ph[nt][0] = ex2h2(pk(s[nt][0] - mn0, s[nt][1] - mn0));
            ph[nt][1] = ex2h2(pk(s[nt][2] - mn1, s[nt][3] - mn1));
            float2 f0 = up(ph[nt][0]);
            float2 f1 = up(ph[nt][1]);
            r0 += f0.x + f0.y;
            r1 += f1.x + f1.y;
        }
        r0 += __shfl_xor_sync(0xffffffffu, r0, 1);
        r0 += __shfl_xor_sync(0xffffffffu, r0, 2);
        r1 += __shfl_xor_sync(0xffffffffu, r1, 1);
        r1 += __shfl_xor_sync(0xffffffffu, r1, 2);
        lq0 = lq0*cr0 + r0;
        lq1 = lq1*cr1 + r1;
#pragma unroll
        for (int nt = 0; nt < 8; nt++) {
            O[nt][0] *= cr0; O[nt][1] *= cr0;
            O[nt][2] *= cr1; O[nt][3] *= cr1;
        }

        // ---- O += P V  (V via ldmatrix.x4.trans) ----
        const int vH = 18432 + buf*18432;
#pragma unroll
        for (int t = 0; t < 4; t++) {
            unsigned pa0 = ph[4*t][0],   pa1 = ph[4*t][1];
            unsigned pa2 = ph[4*t+1][0], pa3 = ph[4*t+1][1];
            unsigned qa0 = ph[4*t+2][0], qa1 = ph[4*t+2][1];
            unsigned qa2 = ph[4*t+3][0], qa3 = ph[4*t+3][1];
#pragma unroll
            for (int nt = 0; nt < 8; nt++) {
                uint32_t vd = sb + (vH + (t*32 + lane)*72 + nt*8)*2;
                unsigned b0, b1, b2, b3;
                ldsm4t(b0, b1, b2, b3, vd);
                mma_f16(O[nt], pa0, pa1, pa2, pa3, b0, b1);
                mma_f16(O[nt], qa0, qa1, qa2, qa3, b2, b3);
            }
        }
        __syncthreads();
        buf ^= 1;
    }

    // ---- epilogue: 1/l; q_mask; write ----
    int q0r = qt*128 + warp*16 + g;
    int q1r = q0r + 8;
    float inv0 = (2*q0r < len) ? (1.0f / lq0) : 0.0f;
    float inv1 = (2*q1r < len) ? (1.0f / lq1) : 0.0f;
#pragma unroll
    for (int nt = 0; nt < 8; nt++) {
        int col = h*HD_ + nt*8 + 2*c;
        *(float2*)&out[((size_t)(b*SP_ + q0r))*(NH_*HD_) + col] =
            make_float2(O[nt][0]*inv0, O[nt][1]*inv0);
        *(float2*)&out[((size_t)(b*SP_ + q1r))*(NH_*HD_) + col] =
            make_float2(O[nt][2]*inv1, O[nt][3]*inv1);
    }
}

// ---------------- launcher ----------------------------------------------------
extern "C" void kernel_launch(void* const* d_in, const int* in_sizes, int n_in,
                              void* d_out, int out_size) {
    const float* hidden = (const float*)d_in[0];
    const void*  mask   = d_in[1];
    const float* W      = (const float*)d_in[2];
    const float* bias   = (const float*)d_in[3];
    float* out = (float*)d_out;

    cvtlen_kernel<<<(CVT_TOT + 511) / 512, 256>>>(hidden, W, mask);

    cudaFuncSetAttribute(qkv_gemm_h, cudaFuncAttributeMaxDynamicSharedMemorySize, GEMM_SMEM);
    dim3 gg(NQKV_/128, (B_*S_)/128);   // (24, 128)
    qkv_gemm_h<<<gg, 256, GEMM_SMEM>>>(bias);

    cudaFuncSetAttribute(attn_h, cudaFuncAttributeMaxDynamicSharedMemorySize, ATTN_SMEM);
    dim3 ga(NH_, B_, SP_/128);         // (16, 8, 8): qt slowest
    attn_h<<<ga, 256, ATTN_SMEM>>>(out);
}

// round 15
// speedup vs baseline: 1.0225x; 1.0225x over previous
#include <cuda_runtime.h>
#include <cuda_fp16.h>
#include <cstdint>
#include <math.h>

#define B_    8
#define S_    2048
#define HID_  1024
#define NH_   16
#define HD_   64
#define SP_   1024
#define NQKV_ 3072
#define QSCALE 0.18033688f   // 0.125 * log2(e)

// ---------------- scratch ----------------------------------------------------
__device__ __half g_ah[B_*S_*HID_];       // half hidden
__device__ __half g_wh[NQKV_*HID_];       // half Wqkv
__device__ __half g_qs[B_*S_*HID_];       // q pre-pool (half)
__device__ __half g_kh[B_*NH_*S_*HD_];    // roped K half
__device__ __half g_vh[B_*NH_*S_*HD_];    // V half
__device__ float2 g_rope[S_*32];          // (cos, sin) per (pos, freq)
__device__ int    g_len[B_];

// ---------------- helpers -----------------------------------------------------
__device__ __forceinline__ void mma_f16(float* d,
        unsigned a0, unsigned a1, unsigned a2, unsigned a3,
        unsigned b0, unsigned b1) {
    asm volatile("mma.sync.aligned.m16n8k16.row.col.f32.f16.f16.f32 "
        "{%0,%1,%2,%3},{%4,%5,%6,%7},{%8,%9},{%0,%1,%2,%3};\n"
        : "+f"(d[0]), "+f"(d[1]), "+f"(d[2]), "+f"(d[3])
        : "r"(a0), "r"(a1), "r"(a2), "r"(a3), "r"(b0), "r"(b1));
}
__device__ __forceinline__ unsigned pk(float lo, float hi) {
    __half2 h = __floats2half2_rn(lo, hi);
    return *reinterpret_cast<unsigned*>(&h);
}
__device__ __forceinline__ float2 up(unsigned x) {
    return __half22float2(*reinterpret_cast<__half2*>(&x));
}
__device__ __forceinline__ unsigned ex2h2(unsigned x) {
    unsigned r; asm("ex2.approx.f16x2 %0, %1;" : "=r"(r) : "r"(x)); return r;
}
__device__ __forceinline__ uint32_t smem_u32(const void* p) {
    uint32_t a;
    asm("{ .reg .u64 t; cvta.to.shared.u64 t, %1; cvt.u32.u64 %0, t; }"
        : "=r"(a) : "l"(p));
    return a;
}
__device__ __forceinline__ void cp16(uint32_t saddr, const void* gptr) {
    asm volatile("cp.async.cg.shared.global [%0], [%1], 16;"
                 :: "r"(saddr), "l"(gptr));
}
__device__ __forceinline__ void cp_commit() { asm volatile("cp.async.commit_group;"); }
template <int N>
__device__ __forceinline__ void cp_wait() {
    asm volatile("cp.async.wait_group %0;" :: "n"(N));
}
__device__ __forceinline__ void ldsm4(unsigned& r0, unsigned& r1, unsigned& r2,
                                      unsigned& r3, uint32_t addr) {
    asm volatile("ldmatrix.sync.aligned.m8n8.x4.shared.b16 {%0,%1,%2,%3}, [%4];"
        : "=r"(r0), "=r"(r1), "=r"(r2), "=r"(r3) : "r"(addr));
}
__device__ __forceinline__ void ldsm4t(unsigned& r0, unsigned& r1, unsigned& r2,
                                       unsigned& r3, uint32_t addr) {
    asm volatile("ldmatrix.sync.aligned.m8n8.x4.trans.shared.b16 {%0,%1,%2,%3}, [%4];"
        : "=r"(r0), "=r"(r1), "=r"(r2), "=r"(r3) : "r"(addr));
}

// ---------------- kernel 1: half pre-convert + rope table + lengths -----------
// MLP=2: each thread handles two independent elements.
#define A4_ (B_*S_*HID_/4)
#define W4_ (NQKV_*HID_/4)
#define RT_ (S_*32)
#define CVT_TOT (A4_ + W4_ + RT_)
__device__ __forceinline__ void cvt_one(int i, const float* hidden, const float* W) {
    if (i < A4_) {
        float4 v = ((const float4*)hidden)[i];
        ((uint2*)g_ah)[i] = make_uint2(pk(v.x, v.y), pk(v.z, v.w));
    } else if (i < A4_ + W4_) {
        int j = i - A4_;
        float4 v = ((const float4*)W)[j];
        ((uint2*)g_wh)[j] = make_uint2(pk(v.x, v.y), pk(v.z, v.w));
    } else {
        int e = i - A4_ - W4_;
        if (e < RT_) {
            int s = e >> 5, ir = e & 31;
            float theta = __expf(-(float)ir * (9.210340371976184f / 32.0f));
            float sn, cs;
            sincosf((float)s * theta, &sn, &cs);
            g_rope[e] = make_float2(cs, sn);
        }
    }
}
__global__ void cvtlen_kernel(const float* __restrict__ hidden,
                              const float* __restrict__ W,
                              const void*  __restrict__ mask) {
    int i0 = blockIdx.x * 512 + threadIdx.x;
    cvt_one(i0, hidden, W);
    cvt_one(i0 + 256, hidden, W);
    if (blockIdx.x == 0) {
        __shared__ int sred[256];
        const int* mi = (const int*)mask;
        int w = mi[16];
        int mode = (w == 1) ? 0 : ((w == 0x3F800000) ? 1 : 2);
        for (int b = 0; b < B_; b++) {
            int cnt = 0;
            for (int s = threadIdx.x; s < S_; s += 256) {
                int v;
                if (mode == 0)      v = (mi[b*S_+s] != 0);
                else if (mode == 1) v = (((const float*)mask)[b*S_+s] != 0.0f);
                else                v = (((const unsigned char*)mask)[b*S_+s] != 0);
                cnt += v;
            }
            sred[threadIdx.x] = cnt;
            __syncthreads();
            for (int st = 128; st > 0; st >>= 1) {
                if (threadIdx.x < st) sred[threadIdx.x] += sred[threadIdx.x + st];
                __syncthreads();
            }
            if (threadIdx.x == 0) g_len[b] = sred[0];
            __syncthreads();
        }
    }
}

// ---------------- kernel 2: QKV GEMM fp16, 128x128 tile, BK=64, 3-stage -------
// 256 threads = 8 warps (2x4), warp 64x32, 2 CTAs/SM. Dead M-blocks exit.
// (R13 mapping: bm = blockIdx.y, bn = blockIdx.x)
#define AST_H (128*72)              // halfs per stage (pitch 72)
#define BSTART (3*AST_H)
#define GEMM_SMEM (6*AST_H*2)       // 110592 B
__global__ __launch_bounds__(256, 2) void qkv_gemm_h(const float* __restrict__ bias) {
    const int bm = blockIdx.y, bn = blockIdx.x;
    {
        int bb0 = (bm*128) >> 11;
        int s00 = (bm*128) & 2047;
        if (s00 >= g_len[bb0]) return;     // dead rows: outputs never read
    }
    extern __shared__ __half hs[];
    const uint32_t sb = smem_u32(hs);
    const int tid = threadIdx.x, warp = tid >> 5, lane = tid & 31;
    const int wm = warp >> 2, wn = warp & 3;
    const int g = lane >> 2, c = lane & 3;
    const __half* Ab = g_ah + (size_t)bm * 128 * HID_;
    const __half* Wb = g_wh + (size_t)bn * 128 * HID_;

#define GISSUE(st, kt) do {                                                        \
        _Pragma("unroll")                                                          \
        for (int ii = 0; ii < 8; ii++) {                                           \
            int e = tid + ii*256;                                                  \
            if (e < 1024) {                                                        \
                int row = e >> 3, ch = e & 7;                                      \
                cp16(sb + ((st)*AST_H + row*72 + ch*8)*2,                          \
                     Ab + (size_t)row*HID_ + (kt)*64 + ch*8);                      \
            } else {                                                               \
                int e2 = e - 1024;                                                 \
                int row = e2 >> 3, ch = e2 & 7;                                    \
                cp16(sb + (BSTART + (st)*AST_H + row*72 + ch*8)*2,                 \
                     Wb + (size_t)row*HID_ + (kt)*64 + ch*8);                      \
            }                                                                      \
        }                                                                          \
    } while (0)

    float acc[4][4][4];
#pragma unroll
    for (int i = 0; i < 4; i++)
#pragma unroll
        for (int j = 0; j < 4; j++)
#pragma unroll
            for (int r = 0; r < 4; r++) acc[i][j][r] = 0.0f;

    GISSUE(0, 0); cp_commit();
    GISSUE(1, 1); cp_commit();

    const int l8  = ((lane >> 3) & 1) * 8;
    const int l16 = ((lane >> 4) & 1) * 8;
    for (int kt = 0; kt < 16; kt++) {
        if (kt + 1 < 16) cp_wait<1>(); else cp_wait<0>();
        __syncthreads();
        if (kt + 2 < 16) { GISSUE((kt + 2) % 3, kt + 2); cp_commit(); }

        const uint32_t abase = sb + ((kt % 3) * AST_H) * 2;
        const uint32_t bbase = sb + (BSTART + (kt % 3) * AST_H) * 2;
#pragma unroll
        for (int ks = 0; ks < 4; ks++) {
            unsigned a[4][4], bf[4][2];
#pragma unroll
            for (int i = 0; i < 4; i++) {
                uint32_t ad = abase +
                    ((wm*64 + i*16 + (lane&7) + l8)*72 + ks*16 + l16)*2;
                ldsm4(a[i][0], a[i][1], a[i][2], a[i][3], ad);
            }
#pragma unroll
            for (int jp = 0; jp < 2; jp++) {
                uint32_t bd = bbase +
                    ((wn*32 + jp*16 + (lane&7) + l16)*72 + ks*16 + l8)*2;
                ldsm4(bf[2*jp][0], bf[2*jp][1], bf[2*jp+1][0], bf[2*jp+1][1], bd);
            }
#pragma unroll
            for (int i = 0; i < 4; i++)
#pragma unroll
                for (int j = 0; j < 4; j++)
                    mma_f16(acc[i][j], a[i][0], a[i][1], a[i][2], a[i][3],
                            bf[j][0], bf[j][1]);
        }
    }

    // epilogue: bias; q -> half staging; K -> RoPE (table) -> half; V -> half
#pragma unroll
    for (int i = 0; i < 4; i++) {
#pragma unroll
        for (int hh = 0; hh < 2; hh++) {
            int m = bm*128 + wm*64 + i*16 + hh*8 + g;
            int bb2 = m >> 11;
            int sq = m & 2047;
#pragma unroll
            for (int j = 0; j < 4; j++) {
                int n = bn*128 + wn*32 + j*8 + 2*c;
                float v0 = acc[i][j][hh*2+0] + bias[n];
                float v1 = acc[i][j][hh*2+1] + bias[n+1];
                if (n < 1024) {
                    *(unsigned*)&g_qs[((size_t)(bb2*S_+sq))*HID_ + n] = pk(v0, v1);
                } else if (n < 2048) {
                    int nn = n - 1024, hd = nn >> 6, dd = nn & 63;
                    float2 cs = g_rope[sq*32 + (dd >> 1)];
                    *(unsigned*)&g_kh[(((size_t)(bb2*NH_+hd))*S_ + sq)*HD_ + dd] =
                        pk(v0*cs.x - v1*cs.y, v1*cs.x + v0*cs.y);
                } else {
                    int nn = n - 2048, hd = nn >> 6, dd = nn & 63;
                    *(unsigned*)&g_vh[(((size_t)(bb2*NH_+hd))*S_ + sq)*HD_ + dd] = pk(v0, v1);
                }
            }
        }
    }
}

// ---------------- kernel 3: flash attention fp16, fused pool+RoPE-Q -----------
// R13 grid (SP/128, NH, B): qt fastest -> adjacent blocks share K/V stream in L2.
// smem halfs: Q[128][72] @0; K(buf) @9216+buf*18432; V(buf) @18432+buf*18432.
#define ATTN_SMEM (46080*2)   // 92160 B
__global__ __launch_bounds__(256, 2) void attn_h(float* __restrict__ out) {
    extern __shared__ __half hs[];
    const uint32_t sb = smem_u32(hs);
    const int qt = blockIdx.x, h = blockIdx.y, b = blockIdx.z;
    const int len = g_len[b];
    const int tid = threadIdx.x, warp = tid >> 5, lane = tid & 31;
    const int g = lane >> 2, c = lane & 3;

    // ---- dead q-tile: all rows masked -> write zeros, skip everything ----
    const int plen = (len + 1) >> 1;
    if (qt * 128 >= plen) {
#pragma unroll
        for (int ii = 0; ii < 8; ii++) {
            int e = tid + ii*256;             // 2048 float4 = 128 rows x 16 f4
            int r = e >> 4, c4 = e & 15;
            *(float4*)&out[((size_t)(b*SP_ + qt*128 + r))*(NH_*HD_) + h*HD_ + c4*4] =
                make_float4(0.f, 0.f, 0.f, 0.f);
        }
        return;
    }

    const int l8  = ((lane >> 3) & 1) * 8;
    const int l16 = ((lane >> 4) & 1) * 8;
    const size_t khb = (size_t)(b*NH_+h)*S_*HD_;

#define KVLOAD(buf, kt) do {                                                       \
        _Pragma("unroll")                                                          \
        for (int ii = 0; ii < 8; ii++) {                                           \
            int e = tid + ii*256;                                                  \
            if (e < 1024) {                                                        \
                int row = e >> 3, ch = e & 7;                                      \
                cp16(sb + (9216 + (buf)*18432 + row*72 + ch*8)*2,                  \
                     g_kh + khb + (size_t)((kt)*128+row)*HD_ + ch*8);              \
            } else {                                                               \
                int e2 = e - 1024;                                                 \
                int row = e2 >> 3, ch = e2 & 7;                                    \
                cp16(sb + (18432 + (buf)*18432 + row*72 + ch*8)*2,                 \
                     g_vh + khb + (size_t)((kt)*128+row)*HD_ + ch*8);              \
            }                                                                      \
        }                                                                          \
    } while (0)
    KVLOAD(0, 0);
    cp_commit();

    // fused pool + RoPE + scale for Q tile (overlaps the KV loads above)
#pragma unroll
    for (int ii = 0; ii < 16; ii++) {
        int e = tid + ii*256;                  // 4096 = 128 rows x 32 pairs
        int r = e >> 5, i = e & 31;
        int p = qt*128 + r;
        int s0 = 2 * p;
        int c0 = (s0 < len), c1 = (s0 + 1 < len);
        float norm = (c0 + c1 > 0) ? (float)(c0 + c1) : 1.0f;
        const __half* row0 = g_qs + ((size_t)(b*S_+s0))*HID_ + h*HD_ + 2*i;
        float2 a = c0 ? __half22float2(*(const __half2*)row0) : make_float2(0.f, 0.f);
        float2 d = c1 ? __half22float2(*(const __half2*)(row0 + HID_)) : make_float2(0.f, 0.f);
        float x0 = (a.x + d.x) / norm;
        float x1 = (a.y + d.y) / norm;
        float2 cs = g_rope[p*32 + i];
        *(unsigned*)&hs[r*72 + 2*i] =
            pk((x0*cs.x - x1*cs.y)*QSCALE, (x1*cs.x + x0*cs.y)*QSCALE);
    }

    float O[8][4];
    float m0 = -1e30f, m1 = -1e30f, lq0 = 0.0f, lq1 = 0.0f;
#pragma unroll
    for (int nt = 0; nt < 8; nt++)
#pragma unroll
        for (int r = 0; r < 4; r++) O[nt][r] = 0.0f;

    const int ntiles = (len + 127) >> 7;
    int buf = 0;

    for (int kt = 0; kt < ntiles; kt++) {
        if (kt + 1 < ntiles) { KVLOAD(buf ^ 1, kt + 1); cp_commit(); cp_wait<1>(); }
        else cp_wait<0>();
        __syncthreads();

        // ---- S = Q K^T  (all frags via ldmatrix.x4) ----
        float s[16][4];
#pragma unroll
        for (int nt = 0; nt < 16; nt++)
#pragma unroll
            for (int r = 0; r < 4; r++) s[nt][r] = 0.0f;

        const int kH = 9216 + buf*18432;
#pragma unroll
        for (int ks = 0; ks < 4; ks++) {
            uint32_t ad = sb + ((warp*16 + (lane&7) + l8)*72 + ks*16 + l16)*2;
            unsigned a0, a1, a2, a3;
            ldsm4(a0, a1, a2, a3, ad);
#pragma unroll
            for (int ntp = 0; ntp < 8; ntp++) {
                uint32_t bd = sb + (kH + (ntp*16 + (lane&7) + l16)*72 + ks*16 + l8)*2;
                unsigned b0, b1, b2, b3;
                ldsm4(b0, b1, b2, b3, bd);
                mma_f16(s[2*ntp],   a0, a1, a2, a3, b0, b1);
                mma_f16(s[2*ntp+1], a0, a1, a2, a3, b2, b3);
            }
        }

        // ---- mask partial tile ----
        if (kt == ntiles - 1 && (len & 127)) {
#pragma unroll
            for (int nt = 0; nt < 16; nt++)
#pragma unroll
                for (int cc = 0; cc < 2; cc++) {
                    int kcol = kt*128 + nt*8 + 2*c + cc;
                    if (kcol >= len) { s[nt][cc] = -1e30f; s[nt][2+cc] = -1e30f; }
                }
        }

        // ---- online max + corr ----
        float mx0 = -1e30f, mx1 = -1e30f;
#pragma unroll
        for (int nt = 0; nt < 16; nt++) {
            mx0 = fmaxf(mx0, fmaxf(s[nt][0], s[nt][1]));
            mx1 = fmaxf(mx1, fmaxf(s[nt][2], s[nt][3]));
        }
        mx0 = fmaxf(mx0, __shfl_xor_sync(0xffffffffu, mx0, 1));
        mx0 = fmaxf(mx0, __shfl_xor_sync(0xffffffffu, mx0, 2));
        mx1 = fmaxf(mx1, __shfl_xor_sync(0xffffffffu, mx1, 1));
        mx1 = fmaxf(mx1, __shfl_xor_sync(0xffffffffu, mx1, 2));
        float mn0 = fmaxf(m0, mx0), mn1 = fmaxf(m1, mx1);
        float cr0 = exp2f(m0 - mn0), cr1 = exp2f(m1 - mn1);
        m0 = mn0; m1 = mn1;

        // ---- exp in fp16x2 (packed = PV a-frags); f32 row sums on FMA pipe ----
        unsigned ph[16][2];
        float r0 = 0.0f, r1 = 0.0f;
#pragma unroll
        for (int nt = 0; nt < 16; nt++) {
            ph[nt][0] = ex2h2(pk(s[nt][0] - mn0, s[nt][1] - mn0));
            ph[nt][1] = ex2h2(pk(s[nt][2] - mn1, s[nt][3] - mn1));
            float2 f0 = up(ph[nt][0]);
            float2 f1 = up(ph[nt][1]);
            r0 += f0.x + f0.y;
            r1 += f1.x + f1.y;
        }
        r0 += __shfl_xor_sync(0xffffffffu, r0, 1);
        r0 += __shfl_xor_sync(0xffffffffu, r0, 2);
        r1 += __shfl_xor_sync(0xffffffffu, r1, 1);
        r1 += __shfl_xor_sync(0xffffffffu, r1, 2);
        lq0 = lq0*cr0 + r0;
        lq1 = lq1*cr1 + r1;
#pragma unroll
        for (int nt = 0; nt < 8; nt++) {
            O[nt][0] *= cr0; O[nt][1] *= cr0;
            O[nt][2] *= cr1; O[nt][3] *= cr1;
        }

        // ---- O += P V  (V via ldmatrix.x4.trans) ----
        const int vH = 18432 + buf*18432;
#pragma unroll
        for (int t = 0; t < 4; t++) {
            unsigned pa0 = ph[4*t][0],   pa1 = ph[4*t][1];
            unsigned pa2 = ph[4*t+1][0], pa3 = ph[4*t+1][1];
            unsigned qa0 = ph[4*t+2][0], qa1 = ph[4*t+2][1];
            unsigned qa2 = ph[4*t+3][0], qa3 = ph[4*t+3][1];
#pragma unroll
            for (int nt = 0; nt < 8; nt++) {
                uint32_t vd = sb + (vH + (t*32 + lane)*72 + nt*8)*2;
                unsigned b0, b1, b2, b3;
                ldsm4t(b0, b1, b2, b3, vd);
                mma_f16(O[nt], pa0, pa1, pa2, pa3, b0, b1);
                mma_f16(O[nt], qa0, qa1, qa2, qa3, b2, b3);
            }
        }
        __syncthreads();
        buf ^= 1;
    }

    // ---- epilogue: 1/l; q_mask; write ----
    int q0r = qt*128 + warp*16 + g;
    int q1r = q0r + 8;
    float inv0 = (2*q0r < len) ? (1.0f / lq0) : 0.0f;
    float inv1 = (2*q1r < len) ? (1.0f / lq1) : 0.0f;
#pragma unroll
    for (int nt = 0; nt < 8; nt++) {
        int col = h*HD_ + nt*8 + 2*c;
        *(float2*)&out[((size_t)(b*SP_ + q0r))*(NH_*HD_) + col] =
            make_float2(O[nt][0]*inv0, O[nt][1]*inv0);
        *(float2*)&out[((size_t)(b*SP_ + q1r))*(NH_*HD_) + col] =
            make_float2(O[nt][2]*inv1, O[nt][3]*inv1);
    }
}

// ---------------- launcher ----------------------------------------------------
extern "C" void kernel_launch(void* const* d_in, const int* in_sizes, int n_in,
                              void* d_out, int out_size) {
    const float* hidden = (const float*)d_in[0];
    const void*  mask   = d_in[1];
    const float* W      = (const float*)d_in[2];
    const float* bias   = (const float*)d_in[3];
    float* out = (float*)d_out;

    cvtlen_kernel<<<(CVT_TOT + 511) / 512, 256>>>(hidden, W, mask);

    cudaFuncSetAttribute(qkv_gemm_h, cudaFuncAttributeMaxDynamicSharedMemorySize, GEMM_SMEM);
    dim3 gg(NQKV_/128, (B_*S_)/128);   // (24, 128) — R13 mapping
    qkv_gemm_h<<<gg, 256, GEMM_SMEM>>>(bias);

    cudaFuncSetAttribute(attn_h, cudaFuncAttributeMaxDynamicSharedMemorySize, ATTN_SMEM);
    dim3 ga(SP_/128, NH_, B_);         // (8, 16, 8) — R13 order, qt fastest
    attn_h<<<ga, 256, ATTN_SMEM>>>(out);
}